// round 1
// baseline (speedup 1.0000x reference)
#include <cuda_runtime.h>
#include <math.h>

#define T_TOK 2048
#define HD    2048
#define ID    768
#define NE    32
#define TOPK  4
#define NPAIR (T_TOK*TOPK)

// ---------------- scratch (__device__ globals; no dynamic alloc) ----------------
__device__ int   g_cnt[NE];
__device__ int   g_off[NE];
__device__ int   g_cur[NE];
__device__ int   g_pair_tok[NPAIR];
__device__ float g_pair_w[NPAIR];
__device__ int   g_tk_id[NPAIR];
__device__ float g_tk_w[NPAIR];
// +64 rows of padding so partially-filled m-tiles can be read harmlessly
__device__ float g_act[(size_t)(NPAIR + 64) * ID];

// ---------------- kernel 0: zero per-expert counters ----------------
__global__ void zero_cnt_kernel() {
    if (threadIdx.x < NE) g_cnt[threadIdx.x] = 0;
}

// ---------------- kernel 1: router (logits -> top4 -> softmax weights) ----------------
__global__ void router_kernel(const float* __restrict__ x, const float* __restrict__ gw) {
    __shared__ float xs[HD];
    __shared__ float lg[NE];
    int t = blockIdx.x;
    const float4* xv  = (const float4*)(x + (size_t)t * HD);
    float4*       xsv = (float4*)xs;
    for (int i = threadIdx.x; i < HD/4; i += blockDim.x) xsv[i] = xv[i];
    __syncthreads();
    int warp = threadIdx.x >> 5, lane = threadIdx.x & 31;
    for (int e = warp; e < NE; e += 8) {
        const float4* w = (const float4*)(gw + (size_t)e * HD);
        float s = 0.f;
        #pragma unroll 4
        for (int h = lane; h < HD/4; h += 32) {
            float4 wv = w[h];
            float4 xr = xsv[h];
            s += wv.x*xr.x + wv.y*xr.y + wv.z*xr.z + wv.w*xr.w;
        }
        #pragma unroll
        for (int o = 16; o; o >>= 1) s += __shfl_xor_sync(0xffffffffu, s, o);
        if (lane == 0) lg[e] = s;
    }
    __syncthreads();
    if (threadIdx.x == 0) {
        int sel[TOPK]; float sv[TOPK];
        unsigned used = 0u;
        #pragma unroll
        for (int k = 0; k < TOPK; k++) {
            float best = -1e30f; int bi = 0;
            for (int e2 = 0; e2 < NE; e2++)
                if (!((used >> e2) & 1u) && lg[e2] > best) { best = lg[e2]; bi = e2; }
            used |= 1u << bi; sel[k] = bi; sv[k] = best;
        }
        // softmax over the selected 4 == renormalized full-softmax top-4
        float mx = sv[0], den = 0.f, ww[TOPK];
        #pragma unroll
        for (int k = 0; k < TOPK; k++) { ww[k] = expf(sv[k] - mx); den += ww[k]; }
        #pragma unroll
        for (int k = 0; k < TOPK; k++) {
            g_tk_id[t*TOPK + k] = sel[k];
            g_tk_w [t*TOPK + k] = ww[k] / den;
            atomicAdd(&g_cnt[sel[k]], 1);
        }
    }
}

// ---------------- kernel 2: exclusive scan of counts ----------------
__global__ void scan_kernel() {
    if (threadIdx.x == 0) {
        int acc = 0;
        for (int e = 0; e < NE; e++) { g_off[e] = acc; g_cur[e] = acc; acc += g_cnt[e]; }
    }
}

// ---------------- kernel 3: fill expert-grouped pair lists ----------------
__global__ void fill_kernel() {
    int p = blockIdx.x * blockDim.x + threadIdx.x;
    if (p >= NPAIR) return;
    int e   = g_tk_id[p];
    int pos = atomicAdd(&g_cur[e], 1);
    g_pair_tok[pos] = p >> 2;
    g_pair_w  [pos] = g_tk_w[p];
}

// ---------------- kernel 4: stage A  (X @ Wg, X @ Wu -> silu(g)*u*w) ----------------
// block: 256 thr (16x16), tile 64(tok) x 64(I), KB=16
__global__ __launch_bounds__(256, 2)
void stageA_kernel(const float* __restrict__ x,
                   const float* __restrict__ Wg, const float* __restrict__ Wu) {
    int e = blockIdx.z;
    int cnt = g_cnt[e];
    int m0 = blockIdx.y * 64;
    if (m0 >= cnt) return;
    int off = g_off[e];
    int n0  = blockIdx.x * 64;

    __shared__ float Xs[16][68];
    __shared__ float Bgs[16][64];
    __shared__ float Bus[16][64];
    __shared__ int   toks[64];
    __shared__ float wts[64];

    int tid = threadIdx.x;
    if (tid < 64) {
        int r = m0 + tid;
        toks[tid] = (r < cnt) ? g_pair_tok[off + r] : 0;
        wts[tid]  = (r < cnt) ? g_pair_w [off + r] : 0.f;
    }
    __syncthreads();

    int lr = tid >> 2;            // 0..63 : X row within tile
    int lk = (tid & 3) * 4;       // 0,4,8,12 : k quad
    const float* xrow = x + (size_t)toks[lr] * HD + lk;

    int br = tid >> 4;            // 0..15 : B k-row
    int bc = (tid & 15) * 4;      // 0..60 : B col quad
    const float* gptr = Wg + (size_t)e * HD * ID + (size_t)br * ID + n0 + bc;
    const float* uptr = Wu + (size_t)e * HD * ID + (size_t)br * ID + n0 + bc;

    int tx = tid & 15, ty = tid >> 4;
    float ag[4][4] = {}, au[4][4] = {};

    for (int k0 = 0; k0 < HD; k0 += 16) {
        float4 xv = *(const float4*)(xrow + k0);
        float4 gv = *(const float4*)(gptr + (size_t)k0 * ID);
        float4 uv = *(const float4*)(uptr + (size_t)k0 * ID);
        __syncthreads();
        Xs[lk+0][lr] = xv.x; Xs[lk+1][lr] = xv.y; Xs[lk+2][lr] = xv.z; Xs[lk+3][lr] = xv.w;
        *(float4*)&Bgs[br][bc] = gv;
        *(float4*)&Bus[br][bc] = uv;
        __syncthreads();
        #pragma unroll
        for (int kk = 0; kk < 16; kk++) {
            float4 xr = *(const float4*)&Xs[kk][ty*4];
            float4 bg = *(const float4*)&Bgs[kk][tx*4];
            float4 bu = *(const float4*)&Bus[kk][tx*4];
            float xa[4] = {xr.x, xr.y, xr.z, xr.w};
            float ga[4] = {bg.x, bg.y, bg.z, bg.w};
            float ua[4] = {bu.x, bu.y, bu.z, bu.w};
            #pragma unroll
            for (int i2 = 0; i2 < 4; i2++)
                #pragma unroll
                for (int j = 0; j < 4; j++) {
                    ag[i2][j] += xa[i2] * ga[j];
                    au[i2][j] += xa[i2] * ua[j];
                }
        }
    }

    #pragma unroll
    for (int i2 = 0; i2 < 4; i2++) {
        int r = m0 + ty*4 + i2;
        if (r >= cnt) continue;
        float wr = wts[ty*4 + i2];
        float4 o;
        float v[4];
        #pragma unroll
        for (int j = 0; j < 4; j++) {
            float g = ag[i2][j];
            float s = g / (1.f + __expf(-g));      // silu
            v[j] = s * au[i2][j] * wr;
        }
        o.x = v[0]; o.y = v[1]; o.z = v[2]; o.w = v[3];
        *(float4*)(g_act + (size_t)(off + r) * ID + n0 + tx*4) = o;
    }
}

// ---------------- kernel 5: stage B  (A @ Wd -> atomic scatter-add into out) ----------------
__global__ __launch_bounds__(256, 2)
void stageB_kernel(const float* __restrict__ Wd, float* __restrict__ out) {
    int e = blockIdx.z;
    int cnt = g_cnt[e];
    int m0 = blockIdx.y * 64;
    if (m0 >= cnt) return;
    int off = g_off[e];
    int n0  = blockIdx.x * 64;

    __shared__ float As[16][68];
    __shared__ float Bs[16][64];
    __shared__ int   toks[64];

    int tid = threadIdx.x;
    if (tid < 64) {
        int r = m0 + tid;
        toks[tid] = (r < cnt) ? g_pair_tok[off + r] : 0;
    }
    __syncthreads();

    int lr = tid >> 2;
    int lk = (tid & 3) * 4;
    const float* arow = g_act + (size_t)(off + m0 + lr) * ID + lk;

    int br = tid >> 4;
    int bc = (tid & 15) * 4;
    const float* bptr = Wd + (size_t)e * ID * HD + (size_t)br * HD + n0 + bc;

    int tx = tid & 15, ty = tid >> 4;
    float acc[4][4] = {};

    for (int k0 = 0; k0 < ID; k0 += 16) {
        float4 av = *(const float4*)(arow + k0);
        float4 bv = *(const float4*)(bptr + (size_t)k0 * HD);
        __syncthreads();
        As[lk+0][lr] = av.x; As[lk+1][lr] = av.y; As[lk+2][lr] = av.z; As[lk+3][lr] = av.w;
        *(float4*)&Bs[br][bc] = bv;
        __syncthreads();
        #pragma unroll
        for (int kk = 0; kk < 16; kk++) {
            float4 ar = *(const float4*)&As[kk][ty*4];
            float4 bb = *(const float4*)&Bs[kk][tx*4];
            float aa[4] = {ar.x, ar.y, ar.z, ar.w};
            float ba[4] = {bb.x, bb.y, bb.z, bb.w};
            #pragma unroll
            for (int i2 = 0; i2 < 4; i2++)
                #pragma unroll
                for (int j = 0; j < 4; j++)
                    acc[i2][j] += aa[i2] * ba[j];
        }
    }

    #pragma unroll
    for (int i2 = 0; i2 < 4; i2++) {
        int r = m0 + ty*4 + i2;
        if (r >= cnt) continue;
        int tok = toks[ty*4 + i2];
        float* po = out + (size_t)tok * HD + n0 + tx*4;
        #pragma unroll
        for (int j = 0; j < 4; j++) atomicAdd(po + j, acc[i2][j]);
    }
}

// ---------------- launch ----------------
extern "C" void kernel_launch(void* const* d_in, const int* in_sizes, int n_in,
                              void* d_out, int out_size) {
    const float* x  = (const float*)d_in[0];   // [1,2048,2048]
    const float* gw = (const float*)d_in[1];   // [32,2048]
    const float* Wg = (const float*)d_in[2];   // [32,2048,768]
    const float* Wu = (const float*)d_in[3];   // [32,2048,768]
    const float* Wd = (const float*)d_in[4];   // [32,768,2048]
    float* out = (float*)d_out;                // [1,2048,2048] fp32

    cudaMemsetAsync(out, 0, (size_t)T_TOK * HD * sizeof(float));
    zero_cnt_kernel<<<1, 32>>>();
    router_kernel<<<T_TOK, 256>>>(x, gw);
    scan_kernel<<<1, 32>>>();
    fill_kernel<<<(NPAIR + 255) / 256, 256>>>();

    dim3 ga(ID / 64, T_TOK / 64, NE);
    stageA_kernel<<<ga, 256>>>(x, Wg, Wu);
    dim3 gb(HD / 64, T_TOK / 64, NE);
    stageB_kernel<<<gb, 256>>>(Wd, out);
}